// round 1
// baseline (speedup 1.0000x reference)
#include <cuda_runtime.h>
#include <math.h>

// SupConLoss collapses algebraically (one-hot embeddings => mask == 0):
// loss = ( N^2*log(N) - (1/T) * sum_i( S[label_i] - feats[i,label_i] ) ) / (N*(N-1))
// where S[c] = column sum of features.

#define N_ROWS 8192
#define D_COLS 300
#define TEMP   0.07
#define TPB    256
#define ROWS_PER_BLOCK 32

__device__ float g_S[D_COLS];        // column sums; zero at load, re-zeroed by k2 each launch
__device__ int   g_label[N_ROWS];    // fully overwritten each launch
__device__ float g_fdiag[N_ROWS];    // feats[i, label_i], fully overwritten each launch

__global__ __launch_bounds__(TPB) void supcon_colsum_label_kernel(
    const float* __restrict__ feats, const float* __restrict__ emb)
{
    const int t = threadIdx.x;
    const int row0 = blockIdx.x * ROWS_PER_BLOCK;
    const int c0 = t;            // always < 300 (t < 256)
    const int c1 = t + TPB;      // valid if < 300 (threads 0..43)
    const bool has_c1 = (c1 < D_COLS);

    float s0 = 0.0f, s1 = 0.0f;

    #pragma unroll 4
    for (int r = 0; r < ROWS_PER_BLOCK; ++r) {
        const int row = row0 + r;
        const float* frow = feats + (size_t)row * D_COLS;
        const float* erow = emb   + (size_t)row * D_COLS;

        float f0 = frow[c0];
        float e0 = erow[c0];
        s0 += f0;
        if (e0 != 0.0f) { g_label[row] = c0; g_fdiag[row] = f0; }

        if (has_c1) {
            float f1 = frow[c1];
            float e1 = erow[c1];
            s1 += f1;
            if (e1 != 0.0f) { g_label[row] = c1; g_fdiag[row] = f1; }
        }
    }

    atomicAdd(&g_S[c0], s0);
    if (has_c1) atomicAdd(&g_S[c1], s1);
}

__global__ __launch_bounds__(TPB) void supcon_finalize_kernel(float* __restrict__ out)
{
    __shared__ double red[TPB];
    const int t = threadIdx.x;

    double acc = 0.0;
    for (int i = t; i < N_ROWS; i += TPB) {
        acc += (double)g_S[g_label[i]] - (double)g_fdiag[i];
    }
    red[t] = acc;
    __syncthreads();

    #pragma unroll
    for (int s = TPB / 2; s > 0; s >>= 1) {
        if (t < s) red[t] += red[t + s];
        __syncthreads();
    }

    if (t == 0) {
        const double Nd = (double)N_ROWS;
        double total = red[0];
        double loss = (Nd * Nd * log(Nd) - total / TEMP) / (Nd * (Nd - 1.0));
        out[0] = (float)loss;
    }
    __syncthreads();

    // Re-zero column sums so the next launch (graph replay) sees clean state.
    for (int c = t; c < D_COLS; c += TPB) g_S[c] = 0.0f;
}

extern "C" void kernel_launch(void* const* d_in, const int* in_sizes, int n_in,
                              void* d_out, int out_size)
{
    const float* feats = (const float*)d_in[0];   // features [8192, 300]
    const float* emb   = (const float*)d_in[1];   // embeddings [8192, 300] (one-hot)
    float* out = (float*)d_out;

    supcon_colsum_label_kernel<<<N_ROWS / ROWS_PER_BLOCK, TPB>>>(feats, emb);
    supcon_finalize_kernel<<<1, TPB>>>(out);
}

// round 3
// speedup vs baseline: 1.6277x; 1.6277x over previous
#include <cuda_runtime.h>
#include <math.h>

// SupConLoss closed form (one-hot embeddings => mask == 0):
//   loss = ( N^2*log(N) - (1/T) * total ) / (N*(N-1))
//   total = sum_c cnt[c]*S[c] - sum_i feats[i, label_i]
// where S[c] = column sum of features, cnt[c] = #rows with label c.
// Single kernel: column-sum pass + last-block-ticket finalize.

#define N_ROWS 8192
#define D_COLS 300
#define TEMP   0.07
#define TPB    256
#define ROWS_PER_BLOCK 8
#define GRID   (N_ROWS / ROWS_PER_BLOCK)   // 1024

__device__ float  g_S[D_COLS];     // column sums (zeroed at load; re-zeroed by last block)
__device__ int    g_cnt[D_COLS];   // label counts
__device__ double g_fd;            // sum of feats[i, label_i]
__device__ unsigned int g_done;    // ticket counter

__global__ __launch_bounds__(TPB) void supcon_fused_kernel(
    const float* __restrict__ feats, const float* __restrict__ emb,
    float* __restrict__ out)
{
    const int t = threadIdx.x;
    const int row0 = blockIdx.x * ROWS_PER_BLOCK;
    const int c0 = t;                 // < 300 always (t < 256)
    const int c1 = t + TPB;           // valid for t < 44
    const bool has_c1 = (c1 < D_COLS);

    float s0 = 0.0f, s1 = 0.0f;
    float fd = 0.0f;
    int cnt0 = 0, cnt1 = 0;

    #pragma unroll
    for (int r = 0; r < ROWS_PER_BLOCK; ++r) {
        const int row = row0 + r;
        const float* frow = feats + (size_t)row * D_COLS;
        const float* erow = emb   + (size_t)row * D_COLS;

        float f0 = frow[c0];
        float e0 = erow[c0];
        s0 += f0;
        if (e0 != 0.0f) { fd += f0; cnt0++; }

        if (has_c1) {
            float f1 = frow[c1];
            float e1 = erow[c1];
            s1 += f1;
            if (e1 != 0.0f) { fd += f1; cnt1++; }
        }
    }

    atomicAdd(&g_S[c0], s0);
    if (has_c1) atomicAdd(&g_S[c1], s1);
    if (cnt0) atomicAdd(&g_cnt[c0], cnt0);
    if (cnt1) atomicAdd(&g_cnt[c1], cnt1);

    // Block-reduce fd, one double atomicAdd per block.
    __shared__ float red_f[TPB];
    red_f[t] = fd;
    __syncthreads();
    #pragma unroll
    for (int s = TPB / 2; s >= 32; s >>= 1) {
        if (t < s) red_f[t] += red_f[t + s];
        __syncthreads();
    }
    if (t < 32) {
        float v = red_f[t];
        #pragma unroll
        for (int o = 16; o > 0; o >>= 1)
            v += __shfl_down_sync(0xffffffffu, v, o);
        if (t == 0 && v != 0.0f) atomicAdd(&g_fd, (double)v);
    }

    // Ticket: last finished block does the 300-term finalize.
    __shared__ bool is_last;
    __threadfence();
    if (t == 0) {
        unsigned int ticket = atomicAdd(&g_done, 1u);
        is_last = (ticket == GRID - 1);
    }
    __syncthreads();
    if (!is_last) return;

    __shared__ double red_d[TPB];
    double acc = 0.0;
    for (int c = t; c < D_COLS; c += TPB)
        acc += (double)g_cnt[c] * (double)g_S[c];
    red_d[t] = acc;
    __syncthreads();
    #pragma unroll
    for (int s = TPB / 2; s > 0; s >>= 1) {
        if (t < s) red_d[t] += red_d[t + s];
        __syncthreads();
    }

    if (t == 0) {
        const double Nd = (double)N_ROWS;
        double total = red_d[0] - g_fd;
        double loss = (Nd * Nd * log(Nd) - total / TEMP) / (Nd * (Nd - 1.0));
        out[0] = (float)loss;
    }
    __syncthreads();

    // Re-zero state for next graph replay.
    for (int c = t; c < D_COLS; c += TPB) { g_S[c] = 0.0f; g_cnt[c] = 0; }
    if (t == 0) { g_fd = 0.0; g_done = 0u; }
}

extern "C" void kernel_launch(void* const* d_in, const int* in_sizes, int n_in,
                              void* d_out, int out_size)
{
    const float* feats = (const float*)d_in[0];   // features [8192, 300]
    const float* emb   = (const float*)d_in[1];   // embeddings [8192, 300] one-hot
    float* out = (float*)d_out;

    supcon_fused_kernel<<<GRID, TPB>>>(feats, emb, out);
}